// round 10
// baseline (speedup 1.0000x reference)
#include <cuda_runtime.h>

#define BH 16
#define NSEQ 2048
#define DD 32
#define MM 64
#define LL 32
#define CC (NSEQ/LL)   // 64 chunks

typedef unsigned long long u64;

// packed f32x2 helpers (Blackwell FFMA2: ptxas never auto-fuses; PTX-only)
__device__ __forceinline__ u64 pk2(float x, float y) {
    u64 r; asm("mov.b64 %0, {%1, %2};" : "=l"(r) : "f"(x), "f"(y)); return r;
}
__device__ __forceinline__ void fma2(u64& d, u64 a, u64 b) {
    asm("fma.rn.f32x2 %0, %1, %2, %0;" : "+l"(d) : "l"(a), "l"(b));
}
__device__ __forceinline__ float2 up2(u64 a) {
    float2 f; asm("mov.b64 {%0, %1}, %2;" : "=f"(f.x), "=f"(f.y) : "l"(a)); return f;
}

#define LN_SQRT_M 2.0794415416798357f   // ln(8): folds the 1/sqrt(64) factor

// Scratch (device globals: no allocation allowed in kernel_launch)
__device__ float g_phi_q[BH*NSEQ*MM];     // 8 MB
__device__ float g_phi_k[BH*NSEQ*MM];     // 8 MB
__device__ float g_skv[BH*CC*MM*DD];      // 8 MB  (chunk KV sums -> exclusive prefix)
__device__ float g_sk [BH*CC*MM];         // 256 KB

// ---------------------------------------------------------------------------
// Kernel 1 (fused): per block = 2 chunks (64 tokens), 256 threads.
// __launch_bounds__(256,4): regs<=64 -> 4 CTA/SM -> 592 slots -> grid 512
// runs in ONE wave (was 2 waves at 72 regs / 3 CTA/SM).
// ---------------------------------------------------------------------------
__global__ void __launch_bounds__(256, 4) phi_sum_kernel(
    const float* __restrict__ q, const float* __restrict__ k,
    const float* __restrict__ v, const float* __restrict__ omega)
{
    __shared__ float om_t[DD*MM];    // [d][m] transposed, 8 KB
    __shared__ float xq[64*DD];      // 8 KB (reused for v in phase 2)
    __shared__ float xk[64*DD];      // 8 KB
    __shared__ float pk_s[64*MM];    // [t][m] 16 KB

    int tid = threadIdx.x;
    int blk = blockIdx.x;                    // bh*32 + cc2
    int bh  = blk >> 5;
    int cc2 = blk & 31;                      // superblock of 2 chunks
    int base_tok = bh*NSEQ + cc2*64;

    // omega[m][d] -> om_t[d][m], conflict-free stores
    {
        int m = tid & 63;
        int d0 = (tid >> 6) * 8;
        #pragma unroll
        for (int jj = 0; jj < 8; jj++) {
            int d = d0 + jj;
            om_t[d*MM + m] = omega[m*DD + d];
        }
    }
    // load 64 tokens of q,k (512 float4 each)
    {
        const float4* q4 = (const float4*)(q + base_tok*DD);
        const float4* k4 = (const float4*)(k + base_tok*DD);
        ((float4*)xq)[tid]       = q4[tid];
        ((float4*)xq)[tid + 256] = q4[tid + 256];
        ((float4*)xk)[tid]       = k4[tid];
        ((float4*)xk)[tid + 256] = k4[tid + 256];
    }
    __syncthreads();

    // --- phi phase: packed FFMA2 accumulation ---
    {
        int tp = tid >> 3;           // 0..31 token pair
        int mg = tid & 7;            // m groups {mg*4..+3} and {32+mg*4..+3}
        int t0 = tp*2, t1 = t0+1;
        const ulonglong2* omu = (const ulonglong2*)om_t;  // 16 per d-row
        const float4* xq4 = (const float4*)xq;            // 8 f4 per token
        const float4* xk4 = (const float4*)xk;

        u64 Aq0[4] = {0,0,0,0}, Aq1[4] = {0,0,0,0};
        u64 Ak0[4] = {0,0,0,0}, Ak1[4] = {0,0,0,0};
        float nq0=0.f, nq1=0.f, nk0=0.f, nk1=0.f;

        #pragma unroll
        for (int dc = 0; dc < 8; dc++) {          // 4 d's per iter
            float4 xq0 = xq4[t0*8 + dc], xq1 = xq4[t1*8 + dc];
            float4 xk0 = xk4[t0*8 + dc], xk1 = xk4[t1*8 + dc];
            float q0l[4] = {xq0.x, xq0.y, xq0.z, xq0.w};
            float q1l[4] = {xq1.x, xq1.y, xq1.z, xq1.w};
            float k0l[4] = {xk0.x, xk0.y, xk0.z, xk0.w};
            float k1l[4] = {xk1.x, xk1.y, xk1.z, xk1.w};
            #pragma unroll
            for (int dd = 0; dd < 4; dd++) {
                int d = dc*4 + dd;
                ulonglong2 o0 = omu[d*16 + mg];       // 8-addr broadcast: CF
                ulonglong2 o1 = omu[d*16 + 8 + mg];
                float a = q0l[dd], b = q1l[dd], c = k0l[dd], e = k1l[dd];
                u64 aa = pk2(a,a), bb = pk2(b,b), cc = pk2(c,c), ee = pk2(e,e);
                fma2(Aq0[0], aa, o0.x); fma2(Aq0[1], aa, o0.y);
                fma2(Aq0[2], aa, o1.x); fma2(Aq0[3], aa, o1.y);
                fma2(Aq1[0], bb, o0.x); fma2(Aq1[1], bb, o0.y);
                fma2(Aq1[2], bb, o1.x); fma2(Aq1[3], bb, o1.y);
                fma2(Ak0[0], cc, o0.x); fma2(Ak0[1], cc, o0.y);
                fma2(Ak0[2], cc, o1.x); fma2(Ak0[3], cc, o1.y);
                fma2(Ak1[0], ee, o0.x); fma2(Ak1[1], ee, o0.y);
                fma2(Ak1[2], ee, o1.x); fma2(Ak1[3], ee, o1.y);
                nq0 += a*a; nq1 += b*b; nk0 += c*c; nk1 += e*e;
            }
        }
        // fold 0.5*||x||^2 and ln(sqrt(M)) into one subtrahend
        nq0 = nq0*0.5f + LN_SQRT_M; nq1 = nq1*0.5f + LN_SQRT_M;
        nk0 = nk0*0.5f + LN_SQRT_M; nk1 = nk1*0.5f + LN_SQRT_M;

        // unpack + exp + store: ACC[0..1] = m lo, ACC[2..3] = m hi
        #define EXPST(ACC, n, tok, PKS) { \
            float2 e0 = up2(ACC[0]), e1 = up2(ACC[1]); \
            float2 e2 = up2(ACC[2]), e3 = up2(ACC[3]); \
            float4 plo, phv; \
            plo.x = __expf(e0.x - n); plo.y = __expf(e0.y - n); \
            plo.z = __expf(e1.x - n); plo.w = __expf(e1.y - n); \
            phv.x = __expf(e2.x - n); phv.y = __expf(e2.y - n); \
            phv.z = __expf(e3.x - n); phv.w = __expf(e3.y - n); \
            if (PKS) { \
                *(float4*)&g_phi_k[(base_tok+tok)*MM + mg*4]      = plo; \
                *(float4*)&g_phi_k[(base_tok+tok)*MM + 32 + mg*4] = phv; \
                *(float4*)&pk_s[(tok)*MM + mg*4]      = plo; \
                *(float4*)&pk_s[(tok)*MM + 32 + mg*4] = phv; \
            } else { \
                *(float4*)&g_phi_q[(base_tok+tok)*MM + mg*4]      = plo; \
                *(float4*)&g_phi_q[(base_tok+tok)*MM + 32 + mg*4] = phv; \
            } }
        EXPST(Aq0, nq0, t0, 0)
        EXPST(Aq1, nq1, t1, 0)
        EXPST(Ak0, nk0, t0, 1)
        EXPST(Ak1, nk1, t1, 1)
        #undef EXPST
    }
    __syncthreads();

    // load v into xq buffer (q dead)
    {
        const float4* v4 = (const float4*)(v + base_tok*DD);
        ((float4*)xq)[tid]       = v4[tid];
        ((float4*)xq)[tid + 256] = v4[tid + 256];
    }
    __syncthreads();

    // --- chunk sums (packed): 128 threads per chunk; thread = (m, d-half) ---
    {
        int ch = tid >> 7;           // chunk 0/1
        int r  = tid & 127;
        int m  = r >> 1;             // 0..63
        int dh = r & 1;              // d half (16 d's = 4 ull2)
        const ulonglong2* vsu = (const ulonglong2*)xq;
        const float* pk = &pk_s[ch*32*MM];
        u64 A[8] = {0,0,0,0,0,0,0,0};
        float ks = 0.f;
        #pragma unroll 8
        for (int t = 0; t < LL; t++) {
            float p = pk[t*MM + m];
            u64 pp = pk2(p, p);
            ulonglong2 w0 = vsu[(ch*32+t)*8 + dh*4 + 0];
            ulonglong2 w1 = vsu[(ch*32+t)*8 + dh*4 + 1];
            ulonglong2 w2 = vsu[(ch*32+t)*8 + dh*4 + 2];
            ulonglong2 w3 = vsu[(ch*32+t)*8 + dh*4 + 3];
            fma2(A[0], pp, w0.x); fma2(A[1], pp, w0.y);
            fma2(A[2], pp, w1.x); fma2(A[3], pp, w1.y);
            fma2(A[4], pp, w2.x); fma2(A[5], pp, w2.y);
            fma2(A[6], pp, w3.x); fma2(A[7], pp, w3.y);
            ks += p;
        }
        int blkc = bh*CC + cc2*2 + ch;
        ulonglong2* skvU = (ulonglong2*)g_skv + (size_t)(blkc*MM + m)*8 + dh*4;
        ulonglong2 s;
        s.x = A[0]; s.y = A[1]; skvU[0] = s;
        s.x = A[2]; s.y = A[3]; skvU[1] = s;
        s.x = A[4]; s.y = A[5]; skvU[2] = s;
        s.x = A[6]; s.y = A[7]; skvU[3] = s;
        if (dh == 0) g_sk[blkc*MM + m] = ks;
    }
}

// ---------------------------------------------------------------------------
// Kernel 2: exclusive prefix scan over chunks (in place), float4 for skv.
// ---------------------------------------------------------------------------
__global__ void scan_kernel()
{
    int idx = blockIdx.x * blockDim.x + threadIdx.x;
    const int NSKV = BH*MM*8;        // float4 series
    if (idx < NSKV) {
        int bh = idx / (MM*8);
        int r  = idx % (MM*8);       // m*8 + d4
        float4* base = (float4*)g_skv + (size_t)bh*CC*MM*8 + r;
        float4 run = {0,0,0,0};
        #pragma unroll 4
        for (int c = 0; c < CC; c++) {
            float4 t = base[(size_t)c*MM*8];
            base[(size_t)c*MM*8] = run;
            run.x += t.x; run.y += t.y; run.z += t.z; run.w += t.w;
        }
    } else if (idx < NSKV + BH*MM) {
        int j  = idx - NSKV;
        int bh = j / MM, m = j % MM;
        float* base = g_sk + bh*CC*MM + m;
        float run = 0.f;
        #pragma unroll 4
        for (int c = 0; c < CC; c++) {
            float t = base[c*MM];
            base[c*MM] = run;
            run += t;
        }
    }
}

// ---------------------------------------------------------------------------
// Kernel 3: per-(bh,chunk) output (packed FFMA2 in both phases).
// ---------------------------------------------------------------------------
__global__ void __launch_bounds__(256) out_kernel(
    const float* __restrict__ v, float* __restrict__ out)
{
    __shared__ float pq_p[LL*68];    // [i][m], row stride 17 f4, 8.5 KB
    __shared__ float buf [MM*DD];    // pk [j][m] in A, then Sp [m][d] in B
    __shared__ float vs  [LL*DD];
    __shared__ float A_p [LL*33];    // [i][j], row stride 33
    __shared__ float kp  [MM];
    __shared__ float den [LL];

    int tid = threadIdx.x;
    int blk = blockIdx.x;
    int base_tok = (blk/CC)*NSEQ + (blk%CC)*LL;

    // Early Sp loads -> registers (consumed after Phase A)
    const float4* gs4 = (const float4*)&g_skv[(size_t)blk*MM*DD];
    float4 sp_r0 = gs4[tid];
    float4 sp_r1 = gs4[tid + 256];

    {
        const float4* gq4 = (const float4*)&g_phi_q[base_tok*MM];
        const float4* gk4 = (const float4*)&g_phi_k[base_tok*MM];
        const float4* gv4 = (const float4*)(v + base_tok*DD);
        float4* pq4w = (float4*)pq_p;
        #pragma unroll
        for (int r = 0; r < 2; r++) {
            int idx = tid + r*256;               // i*16 + m4
            int i = idx >> 4, m4 = idx & 15;
            pq4w[i*17 + m4] = gq4[idx];
            ((float4*)buf)[idx] = gk4[idx];      // pk [j][m]
        }
        ((float4*)vs)[tid] = gv4[tid];
        if (tid < MM) kp[tid] = g_sk[blk*MM + tid];
        if (tid < LL) den[tid] = 1e-6f;
    }
    __syncthreads();

    // --- Phase A: i = lane, warp w owns j = w*4 .. w*4+3; packed dots ---
    {
        int i = tid & 31;
        int w = tid >> 5;
        int j0 = w * 4;
        const ulonglong2* pqU = (const ulonglong2*)pq_p;
        const ulonglong2* pkU = (const ulonglong2*)buf;
        const ulonglong2* kpU = (const ulonglong2*)kp;
        u64 D0=0, D1=0, D2=0, D3=0, QK=0;
        #pragma unroll
        for (int m4 = 0; m4 < 16; m4++) {
            ulonglong2 qv = pqU[i*17 + m4];
            ulonglong2 k0 = pkU[(j0+0)*16 + m4];
            ulonglong2 k1 = pkU[(j0+1)*16 + m4];
            ulonglong2 k2 = pkU[(j0+2)*16 + m4];
            ulonglong2 k3 = pkU[(j0+3)*16 + m4];
            ulonglong2 kv = kpU[m4];
            fma2(D0, qv.x, k0.x); fma2(D0, qv.y, k0.y);
            fma2(D1, qv.x, k1.x); fma2(D1, qv.y, k1.y);
            fma2(D2, qv.x, k2.x); fma2(D2, qv.y, k2.y);
            fma2(D3, qv.x, k3.x); fma2(D3, qv.y, k3.y);
            fma2(QK, qv.x, kv.x); fma2(QK, qv.y, kv.y);
        }
        float2 f0 = up2(D0), f1 = up2(D1), f2 = up2(D2), f3 = up2(D3), fq = up2(QK);
        float a0 = f0.x + f0.y, a1 = f1.x + f1.y;
        float a2 = f2.x + f2.y, a3 = f3.x + f3.y;
        float qk = fq.x + fq.y;
        if (j0+0 > i) a0 = 0.f;
        if (j0+1 > i) a1 = 0.f;
        if (j0+2 > i) a2 = 0.f;
        if (j0+3 > i) a3 = 0.f;
        A_p[i*33 + j0+0] = a0;
        A_p[i*33 + j0+1] = a1;
        A_p[i*33 + j0+2] = a2;
        A_p[i*33 + j0+3] = a3;
        float dpart = a0 + a1 + a2 + a3 + (w == 0 ? qk : 0.f);
        atomicAdd(&den[i], dpart);
    }
    __syncthreads();

    // pk dead: store prefetched Sp registers into buf
    ((float4*)buf)[tid]       = sp_r0;
    ((float4*)buf)[tid + 256] = sp_r1;
    __syncthreads();

    // --- Phase B (packed): i = tid>>3, g = tid&7 ---
    {
        int i = tid >> 3;
        int g = tid & 7;
        const float4* pq4 = (const float4*)pq_p;
        const ulonglong2* SpU = (const ulonglong2*)buf;
        const ulonglong2* vsU = (const ulonglong2*)vs;
        u64 O0 = 0, O1 = 0;     // {o.x,o.y}, {o.z,o.w}
        #pragma unroll
        for (int m4 = 0; m4 < 16; m4++) {
            float4 qv = pq4[i*17 + m4];
            ulonglong2 s0 = SpU[(m4*4+0)*8 + g];
            ulonglong2 s1 = SpU[(m4*4+1)*8 + g];
            ulonglong2 s2 = SpU[(m4*4+2)*8 + g];
            ulonglong2 s3 = SpU[(m4*4+3)*8 + g];
            u64 t;
            t = pk2(qv.x, qv.x); fma2(O0, t, s0.x); fma2(O1, t, s0.y);
            t = pk2(qv.y, qv.y); fma2(O0, t, s1.x); fma2(O1, t, s1.y);
            t = pk2(qv.z, qv.z); fma2(O0, t, s2.x); fma2(O1, t, s2.y);
            t = pk2(qv.w, qv.w); fma2(O0, t, s3.x); fma2(O1, t, s3.y);
        }
        #pragma unroll
        for (int j = 0; j < LL; j++) {
            float a = A_p[i*33 + j];
            u64 aa = pk2(a, a);
            ulonglong2 vv = vsU[j*8 + g];
            fma2(O0, aa, vv.x); fma2(O1, aa, vv.y);
        }
        float dinv = 1.0f / den[i];
        float2 o01 = up2(O0), o23 = up2(O1);
        float4* o4 = (float4*)&out[(base_tok + i)*DD + g*4];
        *o4 = make_float4(o01.x*dinv, o01.y*dinv, o23.x*dinv, o23.y*dinv);
    }
}

// ---------------------------------------------------------------------------
extern "C" void kernel_launch(void* const* d_in, const int* in_sizes, int n_in,
                              void* d_out, int out_size)
{
    const float* q     = (const float*)d_in[0];
    const float* k     = (const float*)d_in[1];
    const float* v     = (const float*)d_in[2];
    const float* omega = (const float*)d_in[3];
    float* out = (float*)d_out;

    phi_sum_kernel<<<BH*CC/2, 256>>>(q, k, v, omega);
    const int scan_threads = BH*MM*8 + BH*MM;
    scan_kernel<<<(scan_threads + 255)/256, 256>>>();
    out_kernel<<<BH*CC, 256>>>(v, out);
}